// round 3
// baseline (speedup 1.0000x reference)
#include <cuda_runtime.h>
#include <cuda_bf16.h>

// AttentionAggregator: out[n] = softmax_k(feats[n,k]·w) weighted sum of feats[n,k]
// feats[n,k] = embed_table[neigh_idx[n,k]]  (gather, D=128, K=10)
//
// One warp per node. Each lane owns 4 dims (float4). Neighbor rows loaded ONCE
// into registers (40 floats/lane), reused for both score and weighted sum.
//
// NOTE: harness delivers the int64 reference indices as int32 (its dtype set is
// {float32, int32, bfloat16}) -> read as const int*.

#define K_NEIGH 10
#define D_DIM   128

__global__ __launch_bounds__(256) void attn_agg_kernel(
    const float* __restrict__ table,   // [VOCAB, 128]
    const float* __restrict__ attn_w,  // [128]
    const int*  __restrict__ nidx,     // [N, 10] (int32)
    float* __restrict__ out,           // [N, 128]
    int n_nodes)
{
    int warp = (int)((blockIdx.x * (unsigned)blockDim.x + threadIdx.x) >> 5);
    int lane = threadIdx.x & 31;
    if (warp >= n_nodes) return;

    // attn_w slice for this lane's 4 dims
    const float4 w4 = __ldg(reinterpret_cast<const float4*>(attn_w) + lane);

    const int* ni = nidx + (long long)warp * K_NEIGH;

    float4 f[K_NEIGH];
    float  s[K_NEIGH];

    // Issue all 10 independent row gathers (MLP=10)
    #pragma unroll
    for (int k = 0; k < K_NEIGH; k++) {
        long long row = (long long)__ldg(ni + k);  // broadcast: same addr all lanes
        f[k] = __ldg(reinterpret_cast<const float4*>(table + row * D_DIM) + lane);
    }

    #pragma unroll
    for (int k = 0; k < K_NEIGH; k++) {
        float p = f[k].x * w4.x + f[k].y * w4.y + f[k].z * w4.z + f[k].w * w4.w;
        // full-warp butterfly reduction -> every lane holds the score
        p += __shfl_xor_sync(0xffffffffu, p, 16);
        p += __shfl_xor_sync(0xffffffffu, p, 8);
        p += __shfl_xor_sync(0xffffffffu, p, 4);
        p += __shfl_xor_sync(0xffffffffu, p, 2);
        p += __shfl_xor_sync(0xffffffffu, p, 1);
        s[k] = p;
    }

    // softmax over K in registers
    float m = s[0];
    #pragma unroll
    for (int k = 1; k < K_NEIGH; k++) m = fmaxf(m, s[k]);
    float sum = 0.0f;
    #pragma unroll
    for (int k = 0; k < K_NEIGH; k++) { s[k] = __expf(s[k] - m); sum += s[k]; }
    float inv = __frcp_rn(sum);

    // weighted sum of register-resident feats
    float4 acc = make_float4(0.f, 0.f, 0.f, 0.f);
    #pragma unroll
    for (int k = 0; k < K_NEIGH; k++) {
        float wk = s[k] * inv;
        acc.x = fmaf(wk, f[k].x, acc.x);
        acc.y = fmaf(wk, f[k].y, acc.y);
        acc.z = fmaf(wk, f[k].z, acc.z);
        acc.w = fmaf(wk, f[k].w, acc.w);
    }

    reinterpret_cast<float4*>(out + (long long)warp * D_DIM)[lane] = acc;
}

extern "C" void kernel_launch(void* const* d_in, const int* in_sizes, int n_in,
                              void* d_out, int out_size)
{
    const float* table  = (const float*)d_in[0];  // [VOCAB*128]
    const float* attn_w = (const float*)d_in[1];  // [128]
    const int*   nidx   = (const int*)d_in[2];    // [N*10] int32

    int n_nodes = in_sizes[2] / K_NEIGH;
    float* out = (float*)d_out;

    const int threads = 256;               // 8 warps -> 8 nodes per block
    int blocks = (n_nodes + 7) / 8;
    attn_agg_kernel<<<blocks, threads>>>(table, attn_w, nidx, out, n_nodes);
}